// round 6
// baseline (speedup 1.0000x reference)
#include <cuda_runtime.h>
#include <cuda_fp16.h>
#include <cstdint>

// Problem constants
#define Bn 256
#define Nn 1152        // 32*6*6 input capsules
#define On 10
#define En 16
#define OE 160         // On*En
#define Dn 8
#define NC 32          // n per k_uhat block
#define K1T (Nn / NC)  // 36 n-tiles in k_uhat
#define BC 32          // b per k_uhat block
#define NTILE 128
#define NTILES 9       // 1152 / 128

// Scratch (device globals)
__device__ __half g_uhat[(size_t)Bn * Nn * OE];  // ~94 MB fp16
__device__ float  g_part0[K1T * Bn * OE];        // k_uhat s0 partials (5.9 MB)
__device__ float  g_part1[NTILES * Bn * OE];     // route iter-1 partials (1.5 MB)
__device__ float  g_part2[NTILES * Bn * OE];     // route iter-2 partials (1.5 MB)

// ---------------------------------------------------------------------------
// squash over E=16 within a warp-half. Requires fully-active warps.
__device__ __forceinline__ float squash_val(float sv) {
    float sq = sv * sv;
    sq += __shfl_xor_sync(0xffffffffu, sq, 1);
    sq += __shfl_xor_sync(0xffffffffu, sq, 2);
    sq += __shfl_xor_sync(0xffffffffu, sq, 4);
    sq += __shfl_xor_sync(0xffffffffu, sq, 8);
    return sv * sq / (1.0f + sq) / (sqrtf(sq) + 1e-6f);
}

// ---------------------------------------------------------------------------
// K1: u_hat[b,n,o,e] = sum_d x[b,n,d] * W[n,o,d,e]  (fp16 out)
//     + fused partial s0: g_part0[tile][b][oe] = sum_{n in tile} u
// grid (36 n-tiles, 8 b-tiles), 320 threads = 4 b-groups x 80 (o,e-pair).
__global__ void k_uhat(const float* __restrict__ x, const float* __restrict__ W) {
    int nb = blockIdx.x * NC;
    int b0 = blockIdx.y * BC;
    int t  = threadIdx.x;              // 0..319

    __shared__ float xs[BC][NC][Dn];   // 32 KB, [b][n][d]
    for (int i = t; i < BC * NC * Dn / 4; i += 320) {  // 2048 float4
        int b = i >> 6, q = i & 63;
        float4 v = *(const float4*)(x + ((size_t)(b0 + b) * Nn + nb) * Dn + q * 4);
        int n = q >> 1, h = q & 1;
        *(float4*)(&xs[b][n][h * 4]) = v;
    }
    __syncthreads();

    int g = t / 80, p = t - g * 80;    // g: b-group (8 b each), p: (o, e-pair)
    int o = p >> 3, e2 = p & 7;        // e = 2*e2, 2*e2+1  -> oe = 2*p

    float2 acc[8];
#pragma unroll
    for (int b = 0; b < 8; b++) acc[b] = make_float2(0.f, 0.f);

    __half2* uh = (__half2*)g_uhat;
    for (int n = 0; n < NC; n++) {
        float2 w[8];
        const float2* wp = (const float2*)(W + (size_t)((nb + n) * On + o) * (Dn * En)) + e2;
#pragma unroll
        for (int d = 0; d < 8; d++) w[d] = wp[d * 8];  // stride En floats = 8 float2
#pragma unroll
        for (int b = 0; b < 8; b++) {
            int bb = g * 8 + b;
            float u0 = 0.f, u1 = 0.f;
#pragma unroll
            for (int d = 0; d < 8; d++) {
                float xv = xs[bb][n][d];
                u0 = fmaf(w[d].x, xv, u0);
                u1 = fmaf(w[d].y, xv, u1);
            }
            acc[b].x += u0; acc[b].y += u1;
            uh[((size_t)(b0 + bb) * Nn + nb + n) * 80 + p] = __floats2half2_rn(u0, u1);
        }
    }
#pragma unroll
    for (int b = 0; b < 8; b++) {
        int bb = g * 8 + b;
        *(float2*)(g_part0 + ((size_t)blockIdx.x * Bn + b0 + bb) * OE + 2 * p) = acc[b];
    }
}

// ---------------------------------------------------------------------------
// Route iteration (ITER = 1 or 2):
//   v is recomputed IN-BLOCK from the global partial buffers (redundant per
//   block, ~29 tiny L2 reads/thread, hidden under the 40KB u-tile load):
//     v0 = squash(0.1 * sum_36 g_part0),  ITER2 adds v1 = squash(sum_9 g_part1)
//   logits = u . v ; softmax over o ; weighted partial sums -> g_part1/2.
//   ITER2 traverses (tile,b) REVERSED to harvest the L2-resident tail of
//   u_hat left behind by ITER1's sequential sweep.
// grid (9 tiles, 256 b), 320 threads, ~54 KB dynamic smem.
template <int ITER>
__global__ void k_route() {
    extern __shared__ char sm[];
    __half2* u_s = (__half2*)sm;                    // 40960 B (128 x 80 half2)
    float* v_s = (float*)(sm + NTILE * OE * 2);     // 640
    float* b1s = v_s + OE;                          // 5120
    float* cs  = b1s + NTILE * On;                  // 5120
    float* sp  = cs + NTILE * On;                   // 2560 (4 x 160)

    int tile = (ITER == 2) ? (NTILES - 1 - (int)blockIdx.x) : (int)blockIdx.x;
    int b    = (ITER == 2) ? (Bn - 1 - (int)blockIdx.y)     : (int)blockIdx.y;
    int t = threadIdx.x;
    int n0 = tile * NTILE;

    // Phase A: load fp16 u tile (40 KB); concurrently reconstruct v in-block.
    const float4* src = (const float4*)(g_uhat + ((size_t)b * Nn + n0) * OE);
    float4* dst = (float4*)u_s;
#pragma unroll
    for (int i = 0; i < 8; i++) dst[t + i * 320] = src[t + i * 320];

    if (t < OE) {
        float a0 = 0.f;
#pragma unroll 4
        for (int tl = 0; tl < K1T; tl++)
            a0 += g_part0[((size_t)tl * Bn + b) * OE + t];
        float v = squash_val(a0 * 0.1f);
        if (ITER == 2) {
            float a1 = 0.f;
#pragma unroll
            for (int tl = 0; tl < NTILES; tl++)
                a1 += g_part1[((size_t)tl * Bn + b) * OE + t];
            v += squash_val(a1);
        }
        v_s[t] = v;
    }
    __syncthreads();

    // Phase B: logits b1[n,o] = dot_e(u, v)
#pragma unroll
    for (int i = 0; i < 4; i++) {
        int pp = t + i * 320;          // 0..1279
        int n = pp / On, o = pp - n * On;
        const __half2* ur = u_s + n * 80 + o * 8;
        const float* vr = v_s + o * En;
        float bb = 0.f;
#pragma unroll
        for (int k = 0; k < 8; k++) {
            float2 uf = __half22float2(ur[k]);
            bb = fmaf(uf.x, vr[2 * k], bb);
            bb = fmaf(uf.y, vr[2 * k + 1], bb);
        }
        b1s[pp] = bb;
    }
    __syncthreads();

    // Phase C: softmax over o, one thread per n
    if (t < NTILE) {
        const float* br = b1s + t * On;
        float m = br[0];
#pragma unroll
        for (int o = 1; o < On; o++) m = fmaxf(m, br[o]);
        float ex[On]; float ssum = 0.f;
#pragma unroll
        for (int o = 0; o < On; o++) { ex[o] = __expf(br[o] - m); ssum += ex[o]; }
        float inv = 1.0f / ssum;
        float* cr = cs + t * On;
#pragma unroll
        for (int o = 0; o < On; o++) cr[o] = ex[o] * inv;
    }
    __syncthreads();

    // Phase D: weighted partial sums (4 n-groups x 80 oe-pairs)
    {
        int g = t / 80, p = t - g * 80;
        int o = p >> 3;
        float2 a = make_float2(0.f, 0.f);
        int nb2 = g * 32;
#pragma unroll 8
        for (int n = nb2; n < nb2 + 32; n++) {
            float c = cs[n * On + o];
            float2 uf = __half22float2(u_s[n * 80 + p]);
            a.x = fmaf(c, uf.x, a.x);
            a.y = fmaf(c, uf.y, a.y);
        }
        *(float2*)(sp + g * OE + 2 * p) = a;
    }
    __syncthreads();
    if (t < OE) {
        float r = ((sp[t] + sp[OE + t]) + sp[2 * OE + t]) + sp[3 * OE + t];
        float* dstp = (ITER == 1) ? g_part1 : g_part2;
        dstp[((size_t)tile * Bn + b) * OE + t] = r;
    }
}

// ---------------------------------------------------------------------------
// Final: v2 = squash(sum_9 g_part2) -> out
__global__ void k_final(float* __restrict__ out) {
    int b = blockIdx.x, t = threadIdx.x;  // 160
    float acc = 0.f;
#pragma unroll
    for (int tl = 0; tl < NTILES; tl++)
        acc += g_part2[((size_t)tl * Bn + b) * OE + t];
    out[b * OE + t] = squash_val(acc);
}

// ---------------------------------------------------------------------------
extern "C" void kernel_launch(void* const* d_in, const int* in_sizes, int n_in,
                              void* d_out, int out_size) {
    const float* x = (const float*)d_in[0];
    const float* W = (const float*)d_in[1];
    if (n_in >= 2 && in_sizes[0] == 1474560) {  // defensive: swapped order
        x = (const float*)d_in[1];
        W = (const float*)d_in[0];
    }
    float* out = (float*)d_out;

    const int smem_route = NTILE * OE * 2 + (OE + 2 * NTILE * On + 4 * OE) * 4;
    cudaFuncSetAttribute(k_route<1>, cudaFuncAttributeMaxDynamicSharedMemorySize, smem_route);
    cudaFuncSetAttribute(k_route<2>, cudaFuncAttributeMaxDynamicSharedMemorySize, smem_route);

    k_uhat<<<dim3(K1T, Bn / BC), 320>>>(x, W);            // u_hat fp16 + s0 partials
    k_route<1><<<dim3(NTILES, Bn), 320, smem_route>>>();  // v0 in-block; iter-1 partials
    k_route<2><<<dim3(NTILES, Bn), 320, smem_route>>>();  // v0+v1 in-block; iter-2 partials (reversed sweep)
    k_final<<<Bn, OE>>>(out);                             // v2 -> d_out
}

// round 7
// speedup vs baseline: 1.0087x; 1.0087x over previous
#include <cuda_runtime.h>
#include <cuda_fp16.h>
#include <cstdint>

// Problem constants
#define Bn 256
#define Nn 1152        // 32*6*6 input capsules
#define On 10
#define En 16
#define OE 160         // On*En
#define Dn 8
#define NC 32          // n per k_uhat block
#define K1T (Nn / NC)  // 36 n-tiles in k_uhat
#define BC 32          // b per k_uhat block
#define NTILE 128
#define NTILES 9       // 1152 / 128

// Scratch (device globals)
__device__ __half g_uhat[(size_t)Bn * Nn * OE];  // ~94 MB fp16
__device__ float  g_part[K1T * Bn * OE];         // per-tile partial s (5.9 MB)
__device__ float  g_v[Bn * OE];                  // v0, then v0+v1 (the logit vector)

typedef unsigned long long u64t;

// packed fp32x2 helpers (Blackwell: 2x fp32 FMA per instruction, full precision)
__device__ __forceinline__ void fma2(u64t& d, u64t a, u64t b) {
    asm("fma.rn.f32x2 %0, %1, %2, %0;" : "+l"(d) : "l"(a), "l"(b));
}
__device__ __forceinline__ void add2(u64t& d, u64t a) {
    asm("add.rn.f32x2 %0, %0, %1;" : "+l"(d) : "l"(a));
}
__device__ __forceinline__ float2 unpack2(u64t v) {
    float2 r;
    asm("mov.b64 {%0, %1}, %2;" : "=f"(r.x), "=f"(r.y) : "l"(v));
    return r;
}

// ---------------------------------------------------------------------------
// squash over E=16 within a warp-half. Requires fully-active warps.
__device__ __forceinline__ float squash_val(float sv) {
    float sq = sv * sv;
    sq += __shfl_xor_sync(0xffffffffu, sq, 1);
    sq += __shfl_xor_sync(0xffffffffu, sq, 2);
    sq += __shfl_xor_sync(0xffffffffu, sq, 4);
    sq += __shfl_xor_sync(0xffffffffu, sq, 8);
    return sv * sq / (1.0f + sq) / (sqrtf(sq) + 1e-6f);
}

// ---------------------------------------------------------------------------
// K1: u_hat[b,n,o,e] = sum_d x[b,n,d] * W[n,o,d,e]  (fp16 out)
//     + fused partial s0 via packed f32x2 FMA.
// x duplicated in smem as (x,x) so one LDS.64 is a packed broadcast operand.
// grid (36 n-tiles, 8 b-tiles), 320 threads = 4 b-groups x 80 (o,e-pair).
__global__ void k_uhat(const float* __restrict__ x, const float* __restrict__ W) {
    int nb = blockIdx.x * NC;
    int b0 = blockIdx.y * BC;
    int t  = threadIdx.x;                 // 0..319

    __shared__ float2 xs[BC][NC][Dn];     // 64 KB, duplicated (x,x)
    for (int i = t; i < BC * NC * Dn / 4; i += 320) {  // 2048 float4 of x
        int b = i >> 6, q = i & 63;
        float4 v = *(const float4*)(x + ((size_t)(b0 + b) * Nn + nb) * Dn + q * 4);
        int n = q >> 1, h = q & 1;
        float4* d0 = (float4*)(&xs[b][n][h * 4]);
        d0[0] = make_float4(v.x, v.x, v.y, v.y);
        d0[1] = make_float4(v.z, v.z, v.w, v.w);
    }
    __syncthreads();

    int g = t / 80, p = t - g * 80;       // g: b-group (8 b each), p: (o, e-pair)
    int o = p >> 3, e2 = p & 7;           // oe = 2*p

    u64t acc[8];
#pragma unroll
    for (int b = 0; b < 8; b++) acc[b] = 0ull;

    __half2* uh = (__half2*)g_uhat;
    const u64t* xp = (const u64t*)&xs[g * 8][0][0];  // base of this group's x rows

    for (int n = 0; n < NC; n++) {
        u64t w[8];
        const u64t* wp = (const u64t*)(W + (size_t)((nb + n) * On + o) * (Dn * En)) + e2;
#pragma unroll
        for (int d = 0; d < 8; d++) w[d] = wp[d * 8];  // stride En floats = 8 u64
#pragma unroll
        for (int b = 0; b < 8; b++) {
            const u64t* xr = xp + (size_t)b * (NC * Dn) + n * Dn;
            u64t la = 0ull;
#pragma unroll
            for (int d = 0; d < 8; d++) fma2(la, w[d], xr[d]);
            add2(acc[b], la);
            float2 uf = unpack2(la);
            uh[((size_t)(b0 + g * 8 + b) * Nn + nb + n) * 80 + p] = __floats2half2_rn(uf.x, uf.y);
        }
    }
#pragma unroll
    for (int b = 0; b < 8; b++) {
        float2 af = unpack2(acc[b]);
        *(float2*)(g_part + ((size_t)blockIdx.x * Bn + b0 + g * 8 + b) * OE + 2 * p) = af;
    }
}

// ---------------------------------------------------------------------------
// Route iteration: logits = u . g_v ; softmax over o ; weighted partial sums.
// g_v holds v0 (iter 1) or v0+v1 (iter 2) — logits are additive from b=0.
// grid (9 tiles, 256 b), 320 threads, ~54 KB dynamic smem.
__global__ void k_route() {
    extern __shared__ char sm[];
    __half2* u_s = (__half2*)sm;                    // 40960 B (128 x 80 half2)
    float* v_s = (float*)(sm + NTILE * OE * 2);     // 640
    float* b1s = v_s + OE;                          // 5120
    float* cs  = b1s + NTILE * On;                  // 5120
    float* sp  = cs + NTILE * On;                   // 2560 (4 x 160)

    int tile = blockIdx.x, b = blockIdx.y, t = threadIdx.x;
    int n0 = tile * NTILE;

    // Phase A: load fp16 u tile (40 KB) + v
    const float4* src = (const float4*)(g_uhat + ((size_t)b * Nn + n0) * OE);
    float4* dst = (float4*)u_s;
#pragma unroll
    for (int i = 0; i < 8; i++) dst[t + i * 320] = src[t + i * 320];
    if (t < OE) v_s[t] = g_v[b * OE + t];
    __syncthreads();

    // Phase B: logits b1[n,o] = dot_e(u, v)
#pragma unroll
    for (int i = 0; i < 4; i++) {
        int pp = t + i * 320;          // 0..1279
        int n = pp / On, o = pp - n * On;
        const __half2* ur = u_s + n * 80 + o * 8;
        const float* vr = v_s + o * En;
        float bb = 0.f;
#pragma unroll
        for (int k = 0; k < 8; k++) {
            float2 uf = __half22float2(ur[k]);
            bb = fmaf(uf.x, vr[2 * k], bb);
            bb = fmaf(uf.y, vr[2 * k + 1], bb);
        }
        b1s[pp] = bb;
    }
    __syncthreads();

    // Phase C: softmax over o, one thread per n
    if (t < NTILE) {
        const float* br = b1s + t * On;
        float m = br[0];
#pragma unroll
        for (int o = 1; o < On; o++) m = fmaxf(m, br[o]);
        float ex[On]; float ssum = 0.f;
#pragma unroll
        for (int o = 0; o < On; o++) { ex[o] = __expf(br[o] - m); ssum += ex[o]; }
        float inv = 1.0f / ssum;
        float* cr = cs + t * On;
#pragma unroll
        for (int o = 0; o < On; o++) cr[o] = ex[o] * inv;
    }
    __syncthreads();

    // Phase D: weighted partial sums (4 n-groups x 80 oe-pairs)
    {
        int g = t / 80, p = t - g * 80;
        int o = p >> 3;
        float2 a = make_float2(0.f, 0.f);
        int nb2 = g * 32;
#pragma unroll 8
        for (int n = nb2; n < nb2 + 32; n++) {
            float c = cs[n * On + o];
            float2 uf = __half22float2(u_s[n * 80 + p]);
            a.x = fmaf(c, uf.x, a.x);
            a.y = fmaf(c, uf.y, a.y);
        }
        *(float2*)(sp + g * OE + 2 * p) = a;
    }
    __syncthreads();
    if (t < OE)
        g_part[((size_t)tile * Bn + b) * OE + t] =
            ((sp[t] + sp[OE + t]) + sp[2 * OE + t]) + sp[3 * OE + t];
}

// ---------------------------------------------------------------------------
// Reduce partials -> s -> squash.
// mode 0: s0 = 0.1*sum(36 tiles), v0 -> g_v
// mode 1: v1 = squash(sum 9 tiles); g_v += v1 (vsum for iter-2 logits)
// mode 2: v2 -> out
__global__ void k_finish(float* out, int mode) {
    int b = blockIdx.x, t = threadIdx.x;  // 160
    float acc = 0.f;
    if (mode == 0) {
#pragma unroll 4
        for (int tl = 0; tl < K1T; tl++) acc += g_part[((size_t)tl * Bn + b) * OE + t];
        g_v[b * OE + t] = squash_val(acc * 0.1f);
    } else {
#pragma unroll
        for (int tl = 0; tl < NTILES; tl++) acc += g_part[((size_t)tl * Bn + b) * OE + t];
        float v = squash_val(acc);
        if (mode == 1) g_v[b * OE + t] += v;
        else           out[b * OE + t] = v;
    }
}

// ---------------------------------------------------------------------------
extern "C" void kernel_launch(void* const* d_in, const int* in_sizes, int n_in,
                              void* d_out, int out_size) {
    const float* x = (const float*)d_in[0];
    const float* W = (const float*)d_in[1];
    if (n_in >= 2 && in_sizes[0] == 1474560) {  // defensive: swapped order
        x = (const float*)d_in[1];
        W = (const float*)d_in[0];
    }
    float* out = (float*)d_out;

    const int smem_route = NTILE * OE * 2 + (OE + 2 * NTILE * On + 4 * OE) * 4;
    cudaFuncSetAttribute(k_route, cudaFuncAttributeMaxDynamicSharedMemorySize, smem_route);

    k_uhat<<<dim3(K1T, Bn / BC), 320>>>(x, W);            // u_hat fp16 + s0 partials (f32x2)
    k_finish<<<Bn, OE>>>(nullptr, 0);                     // v0
    k_route<<<dim3(NTILES, Bn), 320, smem_route>>>();     // iter 1 partials
    k_finish<<<Bn, OE>>>(nullptr, 1);                     // v1, g_v = v0+v1
    k_route<<<dim3(NTILES, Bn), 320, smem_route>>>();     // iter 2 partials
    k_finish<<<Bn, OE>>>(out, 2);                         // v2 -> d_out
}

// round 8
// speedup vs baseline: 1.0550x; 1.0459x over previous
#include <cuda_runtime.h>
#include <cuda_fp16.h>
#include <cstdint>

// Problem constants
#define Bn 256
#define Nn 1152        // 32*6*6 input capsules
#define On 10
#define En 16
#define OE 160         // On*En
#define Dn 8
#define NC 32          // n per k_uhat block
#define K1T (Nn / NC)  // 36 n-tiles in k_uhat
#define BC 32          // b per k_uhat block
#define NTILE 64       // route tile (halved: 6 CTAs/SM, 2x blocks)
#define NTILES 18      // 1152 / 64

// Scratch (device globals)
__device__ __half g_uhat[(size_t)Bn * Nn * OE];  // ~94 MB fp16
__device__ float  g_part[K1T * Bn * OE];         // partials (k_uhat: 36 tiles; route: 18)
__device__ float  g_v[Bn * OE];                  // v0, then v0+v1 (the logit vector)

// ---------------------------------------------------------------------------
// squash over E=16 within a warp-half. Requires fully-active warps.
__device__ __forceinline__ float squash_val(float sv) {
    float sq = sv * sv;
    sq += __shfl_xor_sync(0xffffffffu, sq, 1);
    sq += __shfl_xor_sync(0xffffffffu, sq, 2);
    sq += __shfl_xor_sync(0xffffffffu, sq, 4);
    sq += __shfl_xor_sync(0xffffffffu, sq, 8);
    return sv * sq / (1.0f + sq) / (sqrtf(sq) + 1e-6f);
}

// ---------------------------------------------------------------------------
// K1 (R4 version): u_hat[b,n,o,e] = sum_d x[b,n,d] * W[n,o,d,e]  (fp16 out)
//     + fused partial s0: g_part[tile][b][oe] = sum_{n in tile} u
// grid (36 n-tiles, 8 b-tiles), 320 threads = 4 b-groups x 80 (o,e-pair).
__global__ void k_uhat(const float* __restrict__ x, const float* __restrict__ W) {
    int nb = blockIdx.x * NC;
    int b0 = blockIdx.y * BC;
    int t  = threadIdx.x;              // 0..319

    __shared__ float xs[BC][NC][Dn];   // 32 KB, [b][n][d]
    for (int i = t; i < BC * NC * Dn / 4; i += 320) {  // 2048 float4
        int b = i >> 6, q = i & 63;
        float4 v = *(const float4*)(x + ((size_t)(b0 + b) * Nn + nb) * Dn + q * 4);
        int n = q >> 1, h = q & 1;
        *(float4*)(&xs[b][n][h * 4]) = v;
    }
    __syncthreads();

    int g = t / 80, p = t - g * 80;    // g: b-group (8 b each), p: (o, e-pair)
    int o = p >> 3, e2 = p & 7;        // oe = 2*p

    float2 acc[8];
#pragma unroll
    for (int b = 0; b < 8; b++) acc[b] = make_float2(0.f, 0.f);

    __half2* uh = (__half2*)g_uhat;
    for (int n = 0; n < NC; n++) {
        float2 w[8];
        const float2* wp = (const float2*)(W + (size_t)((nb + n) * On + o) * (Dn * En)) + e2;
#pragma unroll
        for (int d = 0; d < 8; d++) w[d] = wp[d * 8];  // stride En floats = 8 float2
#pragma unroll
        for (int b = 0; b < 8; b++) {
            int bb = g * 8 + b;
            float u0 = 0.f, u1 = 0.f;
#pragma unroll
            for (int d = 0; d < 8; d++) {
                float xv = xs[bb][n][d];
                u0 = fmaf(w[d].x, xv, u0);
                u1 = fmaf(w[d].y, xv, u1);
            }
            acc[b].x += u0; acc[b].y += u1;
            uh[((size_t)(b0 + bb) * Nn + nb + n) * 80 + p] = __floats2half2_rn(u0, u1);
        }
    }
#pragma unroll
    for (int b = 0; b < 8; b++) {
        int bb = g * 8 + b;
        *(float2*)(g_part + ((size_t)blockIdx.x * Bn + b0 + bb) * OE + 2 * p) = acc[b];
    }
}

// ---------------------------------------------------------------------------
// Route iteration: logits = u . g_v ; softmax over o ; weighted partial sums.
// g_v holds v0 (iter 1) or v0+v1 (iter 2) — logits are additive from b=0.
// NTILE=64: grid (18 tiles, 256 b), 320 threads, 28.8 KB smem -> 6 CTAs/SM.
// ITER=2 traverses (tile,b) reversed to harvest L2-resident tail of u_hat.
template <int ITER>
__global__ void k_route() {
    extern __shared__ char sm[];
    __half2* u_s = (__half2*)sm;                    // 20480 B (64 x 80 half2)
    float* v_s = (float*)(sm + NTILE * OE * 2);     // 640 B
    float* b1s = v_s + OE;                          // 2560 B (64 x 10)
    float* cs  = b1s + NTILE * On;                  // 2560 B
    float* sp  = cs + NTILE * On;                   // 2560 B (4 x 160)

    int tile = (ITER == 2) ? (NTILES - 1 - (int)blockIdx.x) : (int)blockIdx.x;
    int b    = (ITER == 2) ? (Bn - 1 - (int)blockIdx.y)     : (int)blockIdx.y;
    int t = threadIdx.x;
    int n0 = tile * NTILE;

    // Phase A: load fp16 u tile (20 KB) + v
    const float4* src = (const float4*)(g_uhat + ((size_t)b * Nn + n0) * OE);
    float4* dst = (float4*)u_s;
#pragma unroll
    for (int i = 0; i < 4; i++) dst[t + i * 320] = src[t + i * 320];
    if (t < OE) v_s[t] = g_v[b * OE + t];
    __syncthreads();

    // Phase B: logits b1[n,o] = dot_e(u, v), vectorized LDS.64
#pragma unroll
    for (int i = 0; i < 2; i++) {
        int pp = t + i * 320;          // 0..639
        int n = pp / On, o = pp - n * On;
        const uint2* ur = (const uint2*)(u_s + n * 80 + o * 8);   // 4 x uint2
        const float2* vf = (const float2*)v_s + o * 8;            // 8 x float2
        float bb = 0.f;
#pragma unroll
        for (int k = 0; k < 4; k++) {
            uint2 uu = ur[k];
            float2 a0 = __half22float2(*(const __half2*)&uu.x);
            float2 a1 = __half22float2(*(const __half2*)&uu.y);
            float2 w0 = vf[2 * k], w1 = vf[2 * k + 1];
            bb = fmaf(a0.x, w0.x, bb);
            bb = fmaf(a0.y, w0.y, bb);
            bb = fmaf(a1.x, w1.x, bb);
            bb = fmaf(a1.y, w1.y, bb);
        }
        b1s[pp] = bb;
    }
    __syncthreads();

    // Phase C: softmax over o, one thread per n
    if (t < NTILE) {
        const float* br = b1s + t * On;
        float m = br[0];
#pragma unroll
        for (int o = 1; o < On; o++) m = fmaxf(m, br[o]);
        float ex[On]; float ssum = 0.f;
#pragma unroll
        for (int o = 0; o < On; o++) { ex[o] = __expf(br[o] - m); ssum += ex[o]; }
        float inv = 1.0f / ssum;
        float* cr = cs + t * On;
#pragma unroll
        for (int o = 0; o < On; o++) cr[o] = ex[o] * inv;
    }
    __syncthreads();

    // Phase D: weighted partial sums (4 n-groups of 16 x 80 oe-pairs)
    {
        int g = t / 80, p = t - g * 80;
        int o = p >> 3;
        float2 a = make_float2(0.f, 0.f);
        int nb2 = g * 16;
#pragma unroll
        for (int n = nb2; n < nb2 + 16; n++) {
            float c = cs[n * On + o];
            float2 uf = __half22float2(u_s[n * 80 + p]);
            a.x = fmaf(c, uf.x, a.x);
            a.y = fmaf(c, uf.y, a.y);
        }
        *(float2*)(sp + g * OE + 2 * p) = a;
    }
    __syncthreads();
    if (t < OE)
        g_part[((size_t)tile * Bn + b) * OE + t] =
            ((sp[t] + sp[OE + t]) + sp[2 * OE + t]) + sp[3 * OE + t];
}

// ---------------------------------------------------------------------------
// Reduce partials -> s -> squash.
// mode 0: s0 = 0.1*sum(36 uhat tiles), v0 -> g_v
// mode 1: v1 = squash(sum 18 route tiles); g_v += v1
// mode 2: v2 -> out
__global__ void k_finish(float* out, int mode) {
    int b = blockIdx.x, t = threadIdx.x;  // 160
    float acc = 0.f;
    if (mode == 0) {
#pragma unroll
        for (int tl = 0; tl < K1T; tl++) acc += g_part[((size_t)tl * Bn + b) * OE + t];
        g_v[b * OE + t] = squash_val(acc * 0.1f);
    } else {
#pragma unroll
        for (int tl = 0; tl < NTILES; tl++) acc += g_part[((size_t)tl * Bn + b) * OE + t];
        float v = squash_val(acc);
        if (mode == 1) g_v[b * OE + t] += v;
        else           out[b * OE + t] = v;
    }
}

// ---------------------------------------------------------------------------
extern "C" void kernel_launch(void* const* d_in, const int* in_sizes, int n_in,
                              void* d_out, int out_size) {
    const float* x = (const float*)d_in[0];
    const float* W = (const float*)d_in[1];
    if (n_in >= 2 && in_sizes[0] == 1474560) {  // defensive: swapped order
        x = (const float*)d_in[1];
        W = (const float*)d_in[0];
    }
    float* out = (float*)d_out;

    const int smem_route = NTILE * OE * 2 + (OE + 2 * NTILE * On + 4 * OE) * 4;  // 28800
    cudaFuncSetAttribute(k_route<1>, cudaFuncAttributeMaxDynamicSharedMemorySize, smem_route);
    cudaFuncSetAttribute(k_route<2>, cudaFuncAttributeMaxDynamicSharedMemorySize, smem_route);

    k_uhat<<<dim3(K1T, Bn / BC), 320>>>(x, W);              // u_hat fp16 + s0 partials
    k_finish<<<Bn, OE>>>(nullptr, 0);                       // v0
    k_route<1><<<dim3(NTILES, Bn), 320, smem_route>>>();    // iter 1 partials
    k_finish<<<Bn, OE>>>(nullptr, 1);                       // v1, g_v = v0+v1
    k_route<2><<<dim3(NTILES, Bn), 320, smem_route>>>();    // iter 2 partials (reversed)
    k_finish<<<Bn, OE>>>(out, 2);                           // v2 -> d_out
}

// round 10
// speedup vs baseline: 1.0763x; 1.0201x over previous
#include <cuda_runtime.h>
#include <cuda_fp16.h>
#include <cstdint>

// Problem constants
#define Bn 256
#define Nn 1152        // 32*6*6 input capsules
#define On 10
#define En 16
#define OE 160         // On*En
#define Dn 8
#define NC 32          // n per k_uhat block
#define K1T (Nn / NC)  // 36 n-tiles in k_uhat
#define BC 32          // b per k_uhat block
#define NTILE 128
#define NTILES 9       // 1152 / 128

// Scratch (device globals)
__device__ __half g_uhat[(size_t)Bn * Nn * OE];  // ~94 MB fp16
__device__ float  g_part[K1T * Bn * OE];         // per-tile partial s (5.9 MB)
__device__ float  g_v[Bn * OE];                  // v0, then v0+v1 (the logit vector)

// ---------------------------------------------------------------------------
// squash over E=16 within a warp-half. Requires fully-active warps.
__device__ __forceinline__ float squash_val(float sv) {
    float sq = sv * sv;
    sq += __shfl_xor_sync(0xffffffffu, sq, 1);
    sq += __shfl_xor_sync(0xffffffffu, sq, 2);
    sq += __shfl_xor_sync(0xffffffffu, sq, 4);
    sq += __shfl_xor_sync(0xffffffffu, sq, 8);
    return sv * sq / (1.0f + sq) / (sqrtf(sq) + 1e-6f);
}

// ---------------------------------------------------------------------------
// K1: u_hat[b,n,o,e] = sum_d x[b,n,d] * W[n,o,d,e]  (fp16 out)
//     + fused partial s0: g_part[tile][b][oe] = sum_{n in tile} u
// grid (36 n-tiles, 8 b-tiles), 320 threads = 4 b-groups x 80 (o,e-pair).
__global__ void k_uhat(const float* __restrict__ x, const float* __restrict__ W) {
    int nb = blockIdx.x * NC;
    int b0 = blockIdx.y * BC;
    int t  = threadIdx.x;              // 0..319

    __shared__ float xs[BC][NC][Dn];   // 32 KB, [b][n][d]
    for (int i = t; i < BC * NC * Dn / 4; i += 320) {  // 2048 float4
        int b = i >> 6, q = i & 63;
        float4 v = *(const float4*)(x + ((size_t)(b0 + b) * Nn + nb) * Dn + q * 4);
        int n = q >> 1, h = q & 1;
        *(float4*)(&xs[b][n][h * 4]) = v;
    }
    __syncthreads();

    int g = t / 80, p = t - g * 80;    // g: b-group (8 b each), p: (o, e-pair)
    int o = p >> 3, e2 = p & 7;        // oe = 2*p

    float2 acc[8];
#pragma unroll
    for (int b = 0; b < 8; b++) acc[b] = make_float2(0.f, 0.f);

    __half2* uh = (__half2*)g_uhat;
    for (int n = 0; n < NC; n++) {
        float2 w[8];
        const float2* wp = (const float2*)(W + (size_t)((nb + n) * On + o) * (Dn * En)) + e2;
#pragma unroll
        for (int d = 0; d < 8; d++) w[d] = wp[d * 8];  // stride En floats = 8 float2
#pragma unroll
        for (int b = 0; b < 8; b++) {
            int bb = g * 8 + b;
            float u0 = 0.f, u1 = 0.f;
#pragma unroll
            for (int d = 0; d < 8; d++) {
                float xv = xs[bb][n][d];
                u0 = fmaf(w[d].x, xv, u0);
                u1 = fmaf(w[d].y, xv, u1);
            }
            acc[b].x += u0; acc[b].y += u1;
            uh[((size_t)(b0 + bb) * Nn + nb + n) * 80 + p] = __floats2half2_rn(u0, u1);
        }
    }
#pragma unroll
    for (int b = 0; b < 8; b++) {
        int bb = g * 8 + b;
        *(float2*)(g_part + ((size_t)blockIdx.x * Bn + b0 + bb) * OE + 2 * p) = acc[b];
    }
}

// ---------------------------------------------------------------------------
// Route iteration: logits = u . g_v ; softmax over o ; weighted partial sums.
// g_v holds v0 (iter 1) or v0+v1 (iter 2) — logits are additive from b=0.
// grid (9 tiles, NB b), 320 threads, ~54 KB dynamic smem. by0 = b offset
// (iter 2 is split into two half-grid launches for ncu visibility).
__global__ void k_route(int by0) {
    extern __shared__ char sm[];
    __half2* u_s = (__half2*)sm;                    // 40960 B (128 x 80 half2)
    float* v_s = (float*)(sm + NTILE * OE * 2);     // 640
    float* b1s = v_s + OE;                          // 5120
    float* cs  = b1s + NTILE * On;                  // 5120
    float* sp  = cs + NTILE * On;                   // 2560 (4 x 160)

    int tile = blockIdx.x, b = blockIdx.y + by0, t = threadIdx.x;
    int n0 = tile * NTILE;

    // Phase A: load fp16 u tile (40 KB) + v
    const float4* src = (const float4*)(g_uhat + ((size_t)b * Nn + n0) * OE);
    float4* dst = (float4*)u_s;
#pragma unroll
    for (int i = 0; i < 8; i++) dst[t + i * 320] = src[t + i * 320];
    if (t < OE) v_s[t] = g_v[b * OE + t];
    __syncthreads();

    // Phase B: logits b1[n,o] = dot_e(u, v)
#pragma unroll
    for (int i = 0; i < 4; i++) {
        int pp = t + i * 320;          // 0..1279
        int n = pp / On, o = pp - n * On;
        const uint2* ur = (const uint2*)(u_s + n * 80 + o * 8);   // 4 x uint2
        const float2* vf = (const float2*)v_s + o * 8;            // 8 x float2
        float bb = 0.f;
#pragma unroll
        for (int k = 0; k < 4; k++) {
            uint2 uu = ur[k];
            float2 a0 = __half22float2(*(const __half2*)&uu.x);
            float2 a1 = __half22float2(*(const __half2*)&uu.y);
            float2 w0 = vf[2 * k], w1 = vf[2 * k + 1];
            bb = fmaf(a0.x, w0.x, bb);
            bb = fmaf(a0.y, w0.y, bb);
            bb = fmaf(a1.x, w1.x, bb);
            bb = fmaf(a1.y, w1.y, bb);
        }
        b1s[pp] = bb;
    }
    __syncthreads();

    // Phase C: softmax over o, one thread per n
    if (t < NTILE) {
        const float* br = b1s + t * On;
        float m = br[0];
#pragma unroll
        for (int o = 1; o < On; o++) m = fmaxf(m, br[o]);
        float ex[On]; float ssum = 0.f;
#pragma unroll
        for (int o = 0; o < On; o++) { ex[o] = __expf(br[o] - m); ssum += ex[o]; }
        float inv = 1.0f / ssum;
        float* cr = cs + t * On;
#pragma unroll
        for (int o = 0; o < On; o++) cr[o] = ex[o] * inv;
    }
    __syncthreads();

    // Phase D: weighted partial sums (4 n-groups x 80 oe-pairs)
    {
        int g = t / 80, p = t - g * 80;
        int o = p >> 3;
        float2 a = make_float2(0.f, 0.f);
        int nb2 = g * 32;
#pragma unroll 8
        for (int n = nb2; n < nb2 + 32; n++) {
            float c = cs[n * On + o];
            float2 uf = __half22float2(u_s[n * 80 + p]);
            a.x = fmaf(c, uf.x, a.x);
            a.y = fmaf(c, uf.y, a.y);
        }
        *(float2*)(sp + g * OE + 2 * p) = a;
    }
    __syncthreads();
    if (t < OE)
        g_part[((size_t)tile * Bn + b) * OE + t] =
            ((sp[t] + sp[OE + t]) + sp[2 * OE + t]) + sp[3 * OE + t];
}

// ---------------------------------------------------------------------------
// Reduce partials -> s -> squash. Tile axis parallelized across thread groups
// (serial chain 36->9 / 9->3 loads), smem cross-group reduce.
// MODE 0: s0 = 0.1*sum(36 tiles) -> v0 -> g_v   (640 thr = 4 x 160)
// MODE 1: v1 = squash(sum 9); g_v += v1         (480 thr = 3 x 160)
// MODE 2: v2 -> out                             (480 thr)
template <int MODE>
__global__ void k_finish(float* __restrict__ out) {
    constexpr int NT  = (MODE == 0) ? K1T : NTILES;  // 36 / 9
    constexpr int G   = (MODE == 0) ? 4 : 3;
    constexpr int PER = NT / G;                      // 9 / 3
    __shared__ float red[G][OE];

    int b = blockIdx.x, t = threadIdx.x;             // G*160
    int g = t / OE, oe = t - g * OE;
    float acc = 0.f;
#pragma unroll
    for (int i = 0; i < PER; i++)
        acc += g_part[((size_t)(g * PER + i) * Bn + b) * OE + oe];
    red[g][oe] = acc;
    __syncthreads();

    if (t < OE) {
        float s = red[0][t];
#pragma unroll
        for (int gg = 1; gg < G; gg++) s += red[gg][t];
        if (MODE == 0)      g_v[b * OE + t]  = squash_val(s * 0.1f);
        else if (MODE == 1) g_v[b * OE + t] += squash_val(s);
        else                out[b * OE + t]  = squash_val(s);
    }
}

// ---------------------------------------------------------------------------
extern "C" void kernel_launch(void* const* d_in, const int* in_sizes, int n_in,
                              void* d_out, int out_size) {
    const float* x = (const float*)d_in[0];
    const float* W = (const float*)d_in[1];
    if (n_in >= 2 && in_sizes[0] == 1474560) {  // defensive: swapped order
        x = (const float*)d_in[1];
        W = (const float*)d_in[0];
    }
    float* out = (float*)d_out;

    const int smem_route = NTILE * OE * 2 + (OE + 2 * NTILE * On + 4 * OE) * 4;  // ~54 KB
    cudaFuncSetAttribute(k_route, cudaFuncAttributeMaxDynamicSharedMemorySize, smem_route);

    // launch slots:                                    #
    k_uhat<<<dim3(K1T, Bn / BC), 320>>>(x, W);       // 0: u_hat fp16 + s0 partials
    k_finish<0><<<Bn, 4 * OE>>>(nullptr);            // 1: v0
    k_route<<<dim3(NTILES, Bn), 320, smem_route>>>(0);       // 2: iter 1 partials
    k_finish<1><<<Bn, 3 * OE>>>(nullptr);            // 3: v1, g_v = v0+v1
    k_route<<<dim3(NTILES, Bn / 2), 320, smem_route>>>(0);   // 4: iter 2, b in [0,128)
    k_route<<<dim3(NTILES, Bn / 2), 320, smem_route>>>(128); // 5: iter 2, b in [128,256)  <- ncu samples this
    k_finish<2><<<Bn, 3 * OE>>>(out);                // 6: v2 -> d_out
}